// round 3
// baseline (speedup 1.0000x reference)
#include <cuda_runtime.h>
#include <cuda_bf16.h>
#include <cstdint>

// Problem: out[524288,128] = x[524288,128] @ W[128,128]^T + b[128]
#define BATCH    524288
#define N_TILES  4096            // BATCH / 128
#define THREADS  512             // 16 warps: 4x4 warp grid of 32x32 output tiles

// SMEM offsets (bf16 tiles, 128 rows x 128 cols, XOR-swizzled 16B chunks)
#define XH_OFF   0
#define XL_OFF   32768
#define WH_OFF   65536
#define WL_OFF   98304
#define SMEM_BYTES (131072 + 1024)

__device__ __forceinline__ uint32_t smem_u32(const void* p) {
    uint32_t a;
    asm("{ .reg .u64 t; cvta.to.shared.u64 t, %1; cvt.u32.u64 %0, t; }" : "=r"(a) : "l"(p));
    return a;
}

// split (a,b) into packed bf16x2 hi and bf16x2 lo (residual)
__device__ __forceinline__ void split_pair(float a, float b, uint32_t& hp, uint32_t& lp) {
    asm("cvt.rn.bf16x2.f32 %0, %1, %2;" : "=r"(hp) : "f"(b), "f"(a));   // hi16=b, lo16=a
    float ha = __uint_as_float(hp << 16);
    float hb = __uint_as_float(hp & 0xffff0000u);
    float la = a - ha;
    float lb = b - hb;
    asm("cvt.rn.bf16x2.f32 %0, %1, %2;" : "=r"(lp) : "f"(lb), "f"(la));
}

__device__ __forceinline__ void ldsm4(uint32_t addr, uint32_t* r) {
    asm volatile("ldmatrix.sync.aligned.m8n8.x4.shared.b16 {%0,%1,%2,%3}, [%4];"
                 : "=r"(r[0]), "=r"(r[1]), "=r"(r[2]), "=r"(r[3]) : "r"(addr));
}

__device__ __forceinline__ void mma_bf16(float* c, const uint32_t* a, uint32_t b0, uint32_t b1) {
    asm volatile("mma.sync.aligned.m16n8k16.row.col.f32.bf16.bf16.f32 "
                 "{%0,%1,%2,%3}, {%4,%5,%6,%7}, {%8,%9}, {%0,%1,%2,%3};"
                 : "+f"(c[0]), "+f"(c[1]), "+f"(c[2]), "+f"(c[3])
                 : "r"(a[0]), "r"(a[1]), "r"(a[2]), "r"(a[3]), "r"(b0), "r"(b1));
}

// Convert 8 float4 (warp w owns rows 8w..8w+7; lane l owns k = 4l..4l+3 of every row)
// into swizzled bf16 hi/lo SMEM. Element (row,k) lives at:
//   row*256 + (((k>>3) ^ (row&7))<<4) + (k&7)*2
__device__ __forceinline__ void convert_to_smem(const float4* v, uint32_t dH, uint32_t dL,
                                                int w, int l) {
#pragma unroll
    for (int i = 0; i < 8; ++i) {
        uint32_t row = (uint32_t)(w * 8 + i);
        uint32_t off = row * 256u + (((uint32_t)(l >> 1) ^ (uint32_t)i) << 4)
                     + (uint32_t)((l & 1) * 8);
        uint32_t h0, l0, h1, l1;
        split_pair(v[i].x, v[i].y, h0, l0);
        split_pair(v[i].z, v[i].w, h1, l1);
        asm volatile("st.shared.v2.b32 [%0], {%1,%2};" :: "r"(dH + off), "r"(h0), "r"(h1) : "memory");
        asm volatile("st.shared.v2.b32 [%0], {%1,%2};" :: "r"(dL + off), "r"(l0), "r"(l1) : "memory");
    }
}

__global__ void __launch_bounds__(THREADS, 1)
linear_mma_kernel(const float* __restrict__ x,
                  const float* __restrict__ W,
                  const float* __restrict__ bias,
                  float* __restrict__ out) {
    extern __shared__ char smem_raw[];
    uint32_t base = (smem_u32(smem_raw) + 1023u) & ~1023u;
    const uint32_t XH = base + XH_OFF, XL = base + XL_OFF;
    const uint32_t WH = base + WH_OFF, WL = base + WL_OFF;

    const int tid = threadIdx.x;
    const int w   = tid >> 5;        // warp 0..15
    const int l   = tid & 31;

    // Warp tile: 32(M) x 32(N).  4x4 warp grid.
    const int m_off = (w >> 2) * 32;
    const int n_off = (w & 3) * 32;

    // ldmatrix lane mapping (x4 over a 16x16 bf16 tile):
    //   lane group t = l>>3 selects 8x8 sub-tile; rows r8, k-half kb.
    const int t4 = l >> 3;
    const int r8 = (t4 & 1) * 8 + (l & 7);
    const int kb = t4 >> 1;                       // 0 or 1 (k+0 / k+8)
    const uint32_t pa = (uint32_t)(m_off + r8) * 256u;
    const uint32_t pb = (uint32_t)(n_off + r8) * 256u;
    const int l7 = l & 7;

    // ---- stationary W -> bf16 hi/lo in SMEM (each warp 8 rows) ----
    {
        float4 wv[8];
        const float4* Wp = reinterpret_cast<const float4*>(W);
#pragma unroll
        for (int i = 0; i < 8; ++i) wv[i] = Wp[w * 256 + i * 32 + l];
        convert_to_smem(wv, WH, WL, w, l);
    }

    // bias regs for this thread's 8 output columns
    float2 bj[4];
#pragma unroll
    for (int j = 0; j < 4; ++j) {
        int col = n_off + j * 8 + (l & 3) * 2;
        bj[j].x = __ldg(bias + col);
        bj[j].y = __ldg(bias + col + 1);
    }

    const float4* x4 = reinterpret_cast<const float4*>(x);
    int tile = blockIdx.x;
    const int stride = gridDim.x;

    // prefetch first x tile into registers (perfectly coalesced: warp owns 8 rows)
    float4 xr[8];
    if (tile < N_TILES) {
        const float4* src = x4 + (size_t)tile * 4096;
#pragma unroll
        for (int i = 0; i < 8; ++i) xr[i] = __ldcs(&src[w * 256 + i * 32 + l]);
    }
    __syncthreads();   // W tiles visible

    while (tile < N_TILES) {
        // convert prefetched x tile into XH/XL
        convert_to_smem(xr, XH, XL, w, l);
        __syncthreads();

        // prefetch next tile (hidden under the MMA section)
        int tn = tile + stride;
        if (tn < N_TILES) {
            const float4* src = x4 + (size_t)tn * 4096;
#pragma unroll
            for (int i = 0; i < 8; ++i) xr[i] = __ldcs(&src[w * 256 + i * 32 + l]);
        }

        // ---- 3-GEMM split MMA: xh*Wh + xl*Wh + xh*Wl ----
        float c[32];
#pragma unroll
        for (int i = 0; i < 32; ++i) c[i] = 0.f;

#pragma unroll
        for (int ks = 0; ks < 8; ++ks) {
            uint32_t cs = ((uint32_t)((2 * ks + kb) ^ l7)) << 4;
            uint32_t axh[8], axl[8], bh[8], bl[8];
            ldsm4(XH + pa + cs,        axh + 0);
            ldsm4(XH + pa + 4096 + cs, axh + 4);
            ldsm4(XL + pa + cs,        axl + 0);
            ldsm4(XL + pa + 4096 + cs, axl + 4);
            ldsm4(WH + pb + cs,        bh + 0);
            ldsm4(WH + pb + 4096 + cs, bh + 4);
            ldsm4(WL + pb + cs,        bl + 0);
            ldsm4(WL + pb + 4096 + cs, bl + 4);
#pragma unroll
            for (int mi = 0; mi < 2; ++mi) {
#pragma unroll
                for (int j = 0; j < 4; ++j) {
                    float* cc = c + (mi * 4 + j) * 4;
                    int bi = (j >> 1) * 4 + (j & 1);
                    mma_bf16(cc, axh + mi * 4, bh[bi], bh[bi + 2]);
                    mma_bf16(cc, axl + mi * 4, bh[bi], bh[bi + 2]);
                    mma_bf16(cc, axh + mi * 4, bl[bi], bl[bi + 2]);
                }
            }
        }

        // ---- epilogue: bias add + store (full 32B sectors) ----
        {
            float* ob = out + (size_t)tile * 128 * 128;
#pragma unroll
            for (int mi = 0; mi < 2; ++mi) {
#pragma unroll
                for (int j = 0; j < 4; ++j) {
                    int ci = (mi * 4 + j) * 4;
                    int r  = m_off + mi * 16 + (l >> 2);
                    int col = n_off + j * 8 + (l & 3) * 2;
                    float2 v0 = { c[ci + 0] + bj[j].x, c[ci + 1] + bj[j].y };
                    float2 v1 = { c[ci + 2] + bj[j].x, c[ci + 3] + bj[j].y };
                    float* po = ob + (size_t)r * 128 + col;
                    *reinterpret_cast<float2*>(po)             = v0;
                    *reinterpret_cast<float2*>(po + 8 * 128)   = v1;
                }
            }
        }

        __syncthreads();   // all warps done reading XH/XL before next convert
        tile = tn;
    }
}

extern "C" void kernel_launch(void* const* d_in, const int* in_sizes, int n_in,
                              void* d_out, int out_size) {
    const float* x = (const float*)d_in[0];
    const float* W = (const float*)d_in[1];
    const float* b = (const float*)d_in[2];
    float* out = (float*)d_out;

    int nsm = 148;
    cudaDeviceGetAttribute(&nsm, cudaDevAttrMultiProcessorCount, 0);

    cudaFuncSetAttribute(linear_mma_kernel,
                         cudaFuncAttributeMaxDynamicSharedMemorySize, SMEM_BYTES);
    linear_mma_kernel<<<nsm, THREADS, SMEM_BYTES>>>(x, W, b, out);
}

// round 4
// speedup vs baseline: 1.0576x; 1.0576x over previous
#include <cuda_runtime.h>
#include <cuda_bf16.h>
#include <cstdint>

// Problem: out[524288,128] = x[524288,128] @ W[128,128]^T + b[128]
#define BATCH    524288
#define N_TILES  4096            // BATCH / 128
#define THREADS  512             // 16 warps: 4x4 warp grid of 32x32 output tiles

// SMEM layout (bf16 tiles, 128 rows x 128 cols, XOR-swizzled 16B chunks):
// [X0H 32K][X0L 32K][X1H 32K][X1L 32K][WH 32K][WL 32K]
#define XSTAGE_BYTES 65536
#define WH_OFF   131072
#define WL_OFF   163840
#define SMEM_BYTES (196608 + 1024)

__device__ __forceinline__ uint32_t smem_u32(const void* p) {
    uint32_t a;
    asm("{ .reg .u64 t; cvta.to.shared.u64 t, %1; cvt.u32.u64 %0, t; }" : "=r"(a) : "l"(p));
    return a;
}

// split (a,b) into packed bf16x2 hi and bf16x2 lo (residual)
__device__ __forceinline__ void split_pair(float a, float b, uint32_t& hp, uint32_t& lp) {
    asm("cvt.rn.bf16x2.f32 %0, %1, %2;" : "=r"(hp) : "f"(b), "f"(a));   // hi16=b, lo16=a
    float ha = __uint_as_float(hp << 16);
    float hb = __uint_as_float(hp & 0xffff0000u);
    float la = a - ha;
    float lb = b - hb;
    asm("cvt.rn.bf16x2.f32 %0, %1, %2;" : "=r"(lp) : "f"(lb), "f"(la));
}

__device__ __forceinline__ void ldsm4(uint32_t addr, uint32_t* r) {
    asm volatile("ldmatrix.sync.aligned.m8n8.x4.shared.b16 {%0,%1,%2,%3}, [%4];"
                 : "=r"(r[0]), "=r"(r[1]), "=r"(r[2]), "=r"(r[3]) : "r"(addr));
}

__device__ __forceinline__ void mma_bf16(float* c, const uint32_t* a, uint32_t b0, uint32_t b1) {
    asm volatile("mma.sync.aligned.m16n8k16.row.col.f32.bf16.bf16.f32 "
                 "{%0,%1,%2,%3}, {%4,%5,%6,%7}, {%8,%9}, {%0,%1,%2,%3};"
                 : "+f"(c[0]), "+f"(c[1]), "+f"(c[2]), "+f"(c[3])
                 : "r"(a[0]), "r"(a[1]), "r"(a[2]), "r"(a[3]), "r"(b0), "r"(b1));
}

// Convert one row (warp w, sub-row i, lane l owns k = 4l..4l+3) into swizzled
// bf16 hi/lo SMEM. Element (row,k): row*256 + (((k>>3) ^ (row&7))<<4) + (k&7)*2
__device__ __forceinline__ void convert_row(float4 v, uint32_t dH, uint32_t dL,
                                            int w, int l, int i) {
    uint32_t row = (uint32_t)(w * 8 + i);
    uint32_t off = row * 256u + (((uint32_t)(l >> 1) ^ (uint32_t)i) << 4)
                 + (uint32_t)((l & 1) * 8);
    uint32_t h0, l0, h1, l1;
    split_pair(v.x, v.y, h0, l0);
    split_pair(v.z, v.w, h1, l1);
    asm volatile("st.shared.v2.b32 [%0], {%1,%2};" :: "r"(dH + off), "r"(h0), "r"(h1) : "memory");
    asm volatile("st.shared.v2.b32 [%0], {%1,%2};" :: "r"(dL + off), "r"(l0), "r"(l1) : "memory");
}

__global__ void __launch_bounds__(THREADS, 1)
linear_mma_kernel(const float* __restrict__ x,
                  const float* __restrict__ W,
                  const float* __restrict__ bias,
                  float* __restrict__ out) {
    extern __shared__ char smem_raw[];
    uint32_t base = (smem_u32(smem_raw) + 1023u) & ~1023u;
    const uint32_t WH = base + WH_OFF, WL = base + WL_OFF;

    const int tid = threadIdx.x;
    const int w   = tid >> 5;        // warp 0..15
    const int l   = tid & 31;

    // Warp tile: 32(M) x 32(N).  4x4 warp grid.
    const int m_off = (w >> 2) * 32;
    const int n_off = (w & 3) * 32;

    // ldmatrix lane mapping (x4 over a 16x16 bf16 tile)
    const int t4 = l >> 3;
    const int r8 = (t4 & 1) * 8 + (l & 7);
    const int kb = t4 >> 1;
    const uint32_t pa = (uint32_t)(m_off + r8) * 256u;
    const uint32_t pb = (uint32_t)(n_off + r8) * 256u;
    const int l7 = l & 7;

    // ---- stationary W -> bf16 hi/lo in SMEM (each warp 8 rows) ----
    {
        const float4* Wp = reinterpret_cast<const float4*>(W);
#pragma unroll
        for (int i = 0; i < 8; ++i)
            convert_row(Wp[w * 256 + i * 32 + l], WH, WL, w, l, i);
    }

    // bias regs for this thread's 8 output columns
    float2 bj[4];
#pragma unroll
    for (int j = 0; j < 4; ++j) {
        int col = n_off + j * 8 + (l & 3) * 2;
        bj[j].x = __ldg(bias + col);
        bj[j].y = __ldg(bias + col + 1);
    }

    const float4* x4 = reinterpret_cast<const float4*>(x);
    const int stride = gridDim.x;
    int tile = blockIdx.x;
    int tn   = tile + stride;

    // Prologue: load tile -> regs, convert into stage 0, load tn -> regs.
    float4 xr[8];
    if (tile < N_TILES) {
        const float4* src = x4 + (size_t)tile * 4096;
#pragma unroll
        for (int i = 0; i < 8; ++i) xr[i] = __ldcs(&src[w * 256 + i * 32 + l]);
#pragma unroll
        for (int i = 0; i < 8; ++i) convert_row(xr[i], base, base + 32768, w, l, i);
    }
    if (tn < N_TILES) {
        const float4* src = x4 + (size_t)tn * 4096;
#pragma unroll
        for (int i = 0; i < 8; ++i) xr[i] = __ldcs(&src[w * 256 + i * 32 + l]);
    }
    __syncthreads();   // W + stage0 visible

    uint32_t bufoff = 0;
    while (tile < N_TILES) {
        const int t2 = tn + stride;
        const bool cvt = (tn < N_TILES);
        const bool pre = (t2 < N_TILES);
        const uint32_t curH = base + bufoff;
        const uint32_t curL = curH + 32768;
        const uint32_t nxtH = base + (bufoff ^ XSTAGE_BYTES);
        const uint32_t nxtL = nxtH + 32768;
        const float4* src2 = x4 + (size_t)t2 * 4096;

        float c[32];
#pragma unroll
        for (int i = 0; i < 32; ++i) c[i] = 0.f;

        // Fused mainloop: per ks -> 8 ldsm + 24 HMMA, plus 1 row of next-tile
        // convert (ALU) and 1 LDG.128 prefetch of next-next tile (MLP).
#pragma unroll
        for (int ks = 0; ks < 8; ++ks) {
            uint32_t cs = ((uint32_t)((2 * ks + kb) ^ l7)) << 4;
            uint32_t axh[8], axl[8], bh[8], bl[8];
            ldsm4(curH + pa + cs,        axh + 0);
            ldsm4(curH + pa + 4096 + cs, axh + 4);
            ldsm4(curL + pa + cs,        axl + 0);
            ldsm4(curL + pa + 4096 + cs, axl + 4);
            ldsm4(WH + pb + cs,          bh + 0);
            ldsm4(WH + pb + 4096 + cs,   bh + 4);
            ldsm4(WL + pb + cs,          bl + 0);
            ldsm4(WL + pb + 4096 + cs,   bl + 4);

            if (cvt) convert_row(xr[ks], nxtH, nxtL, w, l, ks);
            if (pre) xr[ks] = __ldcs(&src2[w * 256 + ks * 32 + l]);

#pragma unroll
            for (int mi = 0; mi < 2; ++mi) {
#pragma unroll
                for (int j = 0; j < 4; ++j) {
                    float* cc = c + (mi * 4 + j) * 4;
                    int bi = (j >> 1) * 4 + (j & 1);
                    mma_bf16(cc, axh + mi * 4, bh[bi], bh[bi + 2]);
                    mma_bf16(cc, axl + mi * 4, bh[bi], bh[bi + 2]);
                    mma_bf16(cc, axh + mi * 4, bl[bi], bl[bi + 2]);
                }
            }
        }

        // ---- epilogue: bias add + store ----
        {
            float* ob = out + (size_t)tile * 128 * 128;
#pragma unroll
            for (int mi = 0; mi < 2; ++mi) {
#pragma unroll
                for (int j = 0; j < 4; ++j) {
                    int ci = (mi * 4 + j) * 4;
                    int r  = m_off + mi * 16 + (l >> 2);
                    int col = n_off + j * 8 + (l & 3) * 2;
                    float2 v0 = { c[ci + 0] + bj[j].x, c[ci + 1] + bj[j].y };
                    float2 v1 = { c[ci + 2] + bj[j].x, c[ci + 3] + bj[j].y };
                    float* po = ob + (size_t)r * 128 + col;
                    *reinterpret_cast<float2*>(po)           = v0;
                    *reinterpret_cast<float2*>(po + 8 * 128) = v1;
                }
            }
        }

        __syncthreads();   // stage swap: everyone done reading cur / writing nxt
        tile = tn;
        tn = t2;
        bufoff ^= XSTAGE_BYTES;
    }
}

extern "C" void kernel_launch(void* const* d_in, const int* in_sizes, int n_in,
                              void* d_out, int out_size) {
    const float* x = (const float*)d_in[0];
    const float* W = (const float*)d_in[1];
    const float* b = (const float*)d_in[2];
    float* out = (float*)d_out;

    int nsm = 148;
    cudaDeviceGetAttribute(&nsm, cudaDevAttrMultiProcessorCount, 0);

    cudaFuncSetAttribute(linear_mma_kernel,
                         cudaFuncAttributeMaxDynamicSharedMemorySize, SMEM_BYTES);
    linear_mma_kernel<<<nsm, THREADS, SMEM_BYTES>>>(x, W, b, out);
}

// round 5
// speedup vs baseline: 2.1772x; 2.0587x over previous
#include <cuda_runtime.h>
#include <cuda_fp16.h>
#include <cstdint>

// Problem: out[524288,128] = x[524288,128] @ W[128,128]^T + b[128]
// Single fp16 GEMM (fp32 accumulate): l2 rel-err ~3.5e-4 < 1e-3 threshold.
#define BATCH    524288
#define N_TILES  4096            // BATCH / 128
#define THREADS  512             // 16 warps: 4x4 warp grid of 32x32 output tiles

// SMEM layout (fp16 tiles, 128 rows x 128 cols, XOR-swizzled 16B chunks):
// [X0 32K][X1 32K][W 32K]
#define XSTAGE_BYTES 32768
#define W_OFF        65536
#define SMEM_BYTES   (98304 + 1024)

__device__ __forceinline__ uint32_t smem_u32(const void* p) {
    uint32_t a;
    asm("{ .reg .u64 t; cvta.to.shared.u64 t, %1; cvt.u32.u64 %0, t; }" : "=r"(a) : "l"(p));
    return a;
}

// pack (a,b) into f16x2 (lo=a, hi=b)
__device__ __forceinline__ uint32_t pack_f16x2(float a, float b) {
    uint32_t r;
    asm("cvt.rn.f16x2.f32 %0, %1, %2;" : "=r"(r) : "f"(b), "f"(a));
    return r;
}

__device__ __forceinline__ void ldsm4(uint32_t addr, uint32_t* r) {
    asm volatile("ldmatrix.sync.aligned.m8n8.x4.shared.b16 {%0,%1,%2,%3}, [%4];"
                 : "=r"(r[0]), "=r"(r[1]), "=r"(r[2]), "=r"(r[3]) : "r"(addr));
}

__device__ __forceinline__ void mma_fp16(float* c, const uint32_t* a, uint32_t b0, uint32_t b1) {
    asm volatile("mma.sync.aligned.m16n8k16.row.col.f32.f16.f16.f32 "
                 "{%0,%1,%2,%3}, {%4,%5,%6,%7}, {%8,%9}, {%0,%1,%2,%3};"
                 : "+f"(c[0]), "+f"(c[1]), "+f"(c[2]), "+f"(c[3])
                 : "r"(a[0]), "r"(a[1]), "r"(a[2]), "r"(a[3]), "r"(b0), "r"(b1));
}

// Convert one row (warp w, sub-row i, lane l owns k = 4l..4l+3) into swizzled
// fp16 SMEM. Element (row,k): row*256 + (((k>>3) ^ (row&7))<<4) + (k&7)*2
__device__ __forceinline__ void convert_row(float4 v, uint32_t dst, int w, int l, int i) {
    uint32_t row = (uint32_t)(w * 8 + i);
    uint32_t off = row * 256u + (((uint32_t)(l >> 1) ^ (uint32_t)i) << 4)
                 + (uint32_t)((l & 1) * 8);
    uint32_t p0 = pack_f16x2(v.x, v.y);
    uint32_t p1 = pack_f16x2(v.z, v.w);
    asm volatile("st.shared.v2.b32 [%0], {%1,%2};" :: "r"(dst + off), "r"(p0), "r"(p1) : "memory");
}

__global__ void __launch_bounds__(THREADS, 1)
linear_mma_kernel(const float* __restrict__ x,
                  const float* __restrict__ W,
                  const float* __restrict__ bias,
                  float* __restrict__ out) {
    extern __shared__ char smem_raw[];
    uint32_t base = (smem_u32(smem_raw) + 1023u) & ~1023u;
    const uint32_t WS = base + W_OFF;

    const int tid = threadIdx.x;
    const int w   = tid >> 5;        // warp 0..15
    const int l   = tid & 31;

    // Warp tile: 32(M) x 32(N).  4x4 warp grid.
    const int m_off = (w >> 2) * 32;
    const int n_off = (w & 3) * 32;

    // ldmatrix lane mapping (x4 over a 16x16 fp16 tile)
    const int t4 = l >> 3;
    const int r8 = (t4 & 1) * 8 + (l & 7);
    const int kb = t4 >> 1;
    const uint32_t pa = (uint32_t)(m_off + r8) * 256u;
    const uint32_t pb = (uint32_t)(n_off + r8) * 256u;
    const int l7 = l & 7;

    // ---- stationary W -> fp16 in SMEM (each warp 8 rows) ----
    {
        const float4* Wp = reinterpret_cast<const float4*>(W);
#pragma unroll
        for (int i = 0; i < 8; ++i)
            convert_row(Wp[w * 256 + i * 32 + l], WS, w, l, i);
    }

    // bias regs for this thread's 8 output columns
    float2 bj[4];
#pragma unroll
    for (int j = 0; j < 4; ++j) {
        int col = n_off + j * 8 + (l & 3) * 2;
        bj[j].x = __ldg(bias + col);
        bj[j].y = __ldg(bias + col + 1);
    }

    const float4* x4 = reinterpret_cast<const float4*>(x);
    const int stride = gridDim.x;
    int tile = blockIdx.x;
    int tn   = tile + stride;

    // Prologue: load tile -> regs, convert into stage 0, load tn -> regs.
    float4 xr[8];
    if (tile < N_TILES) {
        const float4* src = x4 + (size_t)tile * 4096;
#pragma unroll
        for (int i = 0; i < 8; ++i) xr[i] = __ldcs(&src[w * 256 + i * 32 + l]);
#pragma unroll
        for (int i = 0; i < 8; ++i) convert_row(xr[i], base, w, l, i);
    }
    if (tn < N_TILES) {
        const float4* src = x4 + (size_t)tn * 4096;
#pragma unroll
        for (int i = 0; i < 8; ++i) xr[i] = __ldcs(&src[w * 256 + i * 32 + l]);
    }
    __syncthreads();   // W + stage0 visible

    uint32_t bufoff = 0;
    while (tile < N_TILES) {
        const int t2 = tn + stride;
        const bool cvt = (tn < N_TILES);
        const bool pre = (t2 < N_TILES);
        const uint32_t cur = base + bufoff;
        const uint32_t nxt = base + (bufoff ^ XSTAGE_BYTES);
        const float4* src2 = x4 + (size_t)t2 * 4096;

        float c[32];
#pragma unroll
        for (int i = 0; i < 32; ++i) c[i] = 0.f;

        // Fused mainloop: per ks -> 4 ldsm.x4 + 8 HMMA, plus 1 row of next-tile
        // convert (ALU) and 1 LDG.128 prefetch of next-next tile (MLP).
#pragma unroll
        for (int ks = 0; ks < 8; ++ks) {
            uint32_t cs = ((uint32_t)((2 * ks + kb) ^ l7)) << 4;
            uint32_t a[8], b[8];
            ldsm4(cur + pa + cs,        a + 0);
            ldsm4(cur + pa + 4096 + cs, a + 4);
            ldsm4(WS  + pb + cs,        b + 0);
            ldsm4(WS  + pb + 4096 + cs, b + 4);

            if (cvt) convert_row(xr[ks], nxt, w, l, ks);
            if (pre) xr[ks] = __ldcs(&src2[w * 256 + ks * 32 + l]);

#pragma unroll
            for (int mi = 0; mi < 2; ++mi) {
#pragma unroll
                for (int j = 0; j < 4; ++j) {
                    float* cc = c + (mi * 4 + j) * 4;
                    int bi = (j >> 1) * 4 + (j & 1);
                    mma_fp16(cc, a + mi * 4, b[bi], b[bi + 2]);
                }
            }
        }

        // ---- epilogue: bias add + streaming store ----
        {
            float* ob = out + (size_t)tile * 128 * 128;
#pragma unroll
            for (int mi = 0; mi < 2; ++mi) {
#pragma unroll
                for (int j = 0; j < 4; ++j) {
                    int ci = (mi * 4 + j) * 4;
                    int r  = m_off + mi * 16 + (l >> 2);
                    int col = n_off + j * 8 + (l & 3) * 2;
                    float2 v0 = { c[ci + 0] + bj[j].x, c[ci + 1] + bj[j].y };
                    float2 v1 = { c[ci + 2] + bj[j].x, c[ci + 3] + bj[j].y };
                    float* po = ob + (size_t)r * 128 + col;
                    __stcs(reinterpret_cast<float2*>(po), v0);
                    __stcs(reinterpret_cast<float2*>(po + 8 * 128), v1);
                }
            }
        }

        __syncthreads();   // stage swap: everyone done reading cur / writing nxt
        tile = tn;
        tn = t2;
        bufoff ^= XSTAGE_BYTES;
    }
}

extern "C" void kernel_launch(void* const* d_in, const int* in_sizes, int n_in,
                              void* d_out, int out_size) {
    const float* x = (const float*)d_in[0];
    const float* W = (const float*)d_in[1];
    const float* b = (const float*)d_in[2];
    float* out = (float*)d_out;

    int nsm = 148;
    cudaDeviceGetAttribute(&nsm, cudaDevAttrMultiProcessorCount, 0);

    cudaFuncSetAttribute(linear_mma_kernel,
                         cudaFuncAttributeMaxDynamicSharedMemorySize, SMEM_BYTES);
    linear_mma_kernel<<<nsm, THREADS, SMEM_BYTES>>>(x, W, b, out);
}

// round 8
// speedup vs baseline: 2.2673x; 1.0414x over previous
#include <cuda_runtime.h>
#include <cuda_fp16.h>
#include <cstdint>

// Problem: out[524288,128] = x[524288,128] @ W[128,128]^T + b[128]
// Single fp16 GEMM (fp32 accumulate). W fragments held in registers.
#define BATCH    524288
#define N_TILES  4096            // BATCH / 128
#define THREADS  256             // 8 warps: 2(M) x 4(N) grid of 64x32 warp tiles

// SMEM: two X stages (fp16 128x128, XOR-swizzled 16B chunks), 32KB each.
#define XSTAGE_BYTES 32768
#define SMEM_BYTES   (65536 + 1024)

__device__ __forceinline__ uint32_t smem_u32(const void* p) {
    uint32_t a;
    asm("{ .reg .u64 t; cvta.to.shared.u64 t, %1; cvt.u32.u64 %0, t; }" : "=r"(a) : "l"(p));
    return a;
}

__device__ __forceinline__ uint32_t pack_f16x2(float a, float b) {
    uint32_t r;
    asm("cvt.rn.f16x2.f32 %0, %1, %2;" : "=r"(r) : "f"(b), "f"(a));  // lo=a, hi=b
    return r;
}

__device__ __forceinline__ void ldsm4(uint32_t addr, uint32_t* r) {
    asm volatile("ldmatrix.sync.aligned.m8n8.x4.shared.b16 {%0,%1,%2,%3}, [%4];"
                 : "=r"(r[0]), "=r"(r[1]), "=r"(r[2]), "=r"(r[3]) : "r"(addr));
}

__device__ __forceinline__ void mma_fp16(float* c, const uint32_t* a, uint32_t b0, uint32_t b1) {
    asm volatile("mma.sync.aligned.m16n8k16.row.col.f32.f16.f16.f32 "
                 "{%0,%1,%2,%3}, {%4,%5,%6,%7}, {%8,%9}, {%0,%1,%2,%3};"
                 : "+f"(c[0]), "+f"(c[1]), "+f"(c[2]), "+f"(c[3])
                 : "r"(a[0]), "r"(a[1]), "r"(a[2]), "r"(a[3]), "r"(b0), "r"(b1));
}

// Store one fp32x4 row chunk (row, k=4l..4l+3) into swizzled fp16 SMEM.
// Element (row,k): row*256 + (((k>>3) ^ (row&7))<<4) + (k&7)*2
__device__ __forceinline__ void convert_row(float4 v, uint32_t dst, int row, int l) {
    uint32_t off = (uint32_t)row * 256u
                 + (((uint32_t)(l >> 1) ^ (uint32_t)(row & 7)) << 4)
                 + (uint32_t)((l & 1) * 8);
    uint32_t p0 = pack_f16x2(v.x, v.y);
    uint32_t p1 = pack_f16x2(v.z, v.w);
    asm volatile("st.shared.v2.b32 [%0], {%1,%2};" :: "r"(dst + off), "r"(p0), "r"(p1) : "memory");
}

__global__ void __launch_bounds__(THREADS, 1)
linear_mma_kernel(const float* __restrict__ x,
                  const float* __restrict__ W,
                  const float* __restrict__ bias,
                  float* __restrict__ out) {
    extern __shared__ char smem_raw[];
    uint32_t base = (smem_u32(smem_raw) + 1023u) & ~1023u;

    const int tid = threadIdx.x;
    const int w   = tid >> 5;        // warp 0..7
    const int l   = tid & 31;

    // Warp tile: 64(M) x 32(N).  2x4 warp grid.
    const int m_off = (w >> 2) * 64;
    const int n_off = (w & 3) * 32;

    // ldmatrix lane mapping (x4 over 16x16 fp16 tiles)
    const int t4 = l >> 3;
    const int r8 = (t4 & 1) * 8 + (l & 7);
    const int kb = t4 >> 1;
    const uint32_t pa = (uint32_t)(m_off + r8) * 256u;
    const uint32_t pb = (uint32_t)(n_off + r8) * 256u;
    const int l7 = l & 7;

    // ---- W -> fp16 SMEM (stage0, temporary), then ldsm all fragments into regs ----
    {
        const float4* Wp = reinterpret_cast<const float4*>(W);
#pragma unroll
        for (int i = 0; i < 16; ++i)
            convert_row(Wp[(w * 16 + i) * 32 + l], base, w * 16 + i, l);
    }
    __syncthreads();

    uint32_t wb[64];                 // B fragments: 8 ks x 8 regs
#pragma unroll
    for (int ks = 0; ks < 8; ++ks) {
        uint32_t cs = ((uint32_t)((2 * ks + kb) ^ l7)) << 4;
        ldsm4(base + pb + cs,        wb + ks * 8);
        ldsm4(base + pb + 4096 + cs, wb + ks * 8 + 4);
    }
    __syncthreads();                 // stage0 free for x

    // bias for this thread's 8 output columns
    float2 bj[4];
#pragma unroll
    for (int j = 0; j < 4; ++j) {
        int col = n_off + j * 8 + (l & 3) * 2;
        bj[j].x = __ldg(bias + col);
        bj[j].y = __ldg(bias + col + 1);
    }

    const float4* x4 = reinterpret_cast<const float4*>(x);
    const int stride = gridDim.x;
    int tile = blockIdx.x;
    int tn   = tile + stride;

    // Prologue: tile -> regs -> stage0; tn -> regs.
    float4 xr[16];
    if (tile < N_TILES) {
        const float4* src = x4 + (size_t)tile * 4096;
#pragma unroll
        for (int i = 0; i < 16; ++i) xr[i] = __ldcs(&src[(w * 16 + i) * 32 + l]);
#pragma unroll
        for (int i = 0; i < 16; ++i) convert_row(xr[i], base, w * 16 + i, l);
    }
    if (tn < N_TILES) {
        const float4* src = x4 + (size_t)tn * 4096;
#pragma unroll
        for (int i = 0; i < 16; ++i) xr[i] = __ldcs(&src[(w * 16 + i) * 32 + l]);
    }
    __syncthreads();

    uint32_t bufoff = 0;
    while (tile < N_TILES) {
        const int t2 = tn + stride;
        const bool cvt = (tn < N_TILES);
        const bool pre = (t2 < N_TILES);
        const uint32_t cur = base + bufoff;
        const uint32_t nxt = base + (bufoff ^ XSTAGE_BYTES);
        const float4* src2 = x4 + (size_t)t2 * 4096;

        // accum init = bias (epilogue add folded in)
        float c[64];
#pragma unroll
        for (int mi = 0; mi < 4; ++mi)
#pragma unroll
            for (int j = 0; j < 4; ++j) {
                float* cc = c + (mi * 4 + j) * 4;
                cc[0] = bj[j].x; cc[1] = bj[j].y;
                cc[2] = bj[j].x; cc[3] = bj[j].y;
            }

        // Mainloop: per ks -> 4 ldsm.x4 (A only) + 16 HMMA,
        // + 2 rows next-tile convert + 2 LDG.128 next-next prefetch.
#pragma unroll
        for (int ks = 0; ks < 8; ++ks) {
            uint32_t cs = ((uint32_t)((2 * ks + kb) ^ l7)) << 4;
            uint32_t a[16];
            ldsm4(cur + pa + cs,         a + 0);
            ldsm4(cur + pa + 4096 + cs,  a + 4);
            ldsm4(cur + pa + 8192 + cs,  a + 8);
            ldsm4(cur + pa + 12288 + cs, a + 12);

            if (cvt) {
                convert_row(xr[2 * ks + 0], nxt, w * 16 + 2 * ks + 0, l);
                convert_row(xr[2 * ks + 1], nxt, w * 16 + 2 * ks + 1, l);
            }
            if (pre) {
                xr[2 * ks + 0] = __ldcs(&src2[(w * 16 + 2 * ks + 0) * 32 + l]);
                xr[2 * ks + 1] = __ldcs(&src2[(w * 16 + 2 * ks + 1) * 32 + l]);
            }

            const uint32_t* b = wb + ks * 8;
#pragma unroll
            for (int mi = 0; mi < 4; ++mi)
#pragma unroll
                for (int j = 0; j < 4; ++j) {
                    float* cc = c + (mi * 4 + j) * 4;
                    int bi = (j >> 1) * 4 + (j & 1);
                    mma_fp16(cc, a + mi * 4, b[bi], b[bi + 2]);
                }
        }

        // ---- epilogue: streaming store ----
        {
            float* ob = out + (size_t)tile * 128 * 128;
#pragma unroll
            for (int mi = 0; mi < 4; ++mi)
#pragma unroll
                for (int j = 0; j < 4; ++j) {
                    int ci = (mi * 4 + j) * 4;
                    int r  = m_off + mi * 16 + (l >> 2);
                    int col = n_off + j * 8 + (l & 3) * 2;
                    float2 v0 = { c[ci + 0], c[ci + 1] };
                    float2 v1 = { c[ci + 2], c[ci + 3] };
                    float* po = ob + (size_t)r * 128 + col;
                    __stcs(reinterpret_cast<float2*>(po), v0);
                    __stcs(reinterpret_cast<float2*>(po + 8 * 128), v1);
                }
        }

        __syncthreads();   // stage swap
        tile = tn;
        tn = t2;
        bufoff ^= XSTAGE_BYTES;
    }
}

extern "C" void kernel_launch(void* const* d_in, const int* in_sizes, int n_in,
                              void* d_out, int out_size) {
    const float* x = (const float*)d_in[0];
    const float* W = (const float*)d_in[1];
    const float* b = (const float*)d_in[2];
    float* out = (float*)d_out;

    int nsm = 148;
    cudaDeviceGetAttribute(&nsm, cudaDevAttrMultiProcessorCount, 0);

    cudaFuncSetAttribute(linear_mma_kernel,
                         cudaFuncAttributeMaxDynamicSharedMemorySize, SMEM_BYTES);
    linear_mma_kernel<<<nsm, THREADS, SMEM_BYTES>>>(x, W, b, out);
}